// round 5
// baseline (speedup 1.0000x reference)
#include <cuda_runtime.h>
#include <math.h>

#define NN 10000
#define EE 256000
#define NBINS 2048
#define RMAXF 3.5f
#define INV_SQRT32 0.17677669529663687f
#define INV_SQRT_NAVG 0.19764235376052372f

// ---- static device scratch (no allocations allowed) ----
__device__ float  g_featA[NN * 512];
__device__ float  g_featB[NN * 512];
__device__ int    g_deg[NN];
__device__ int    g_rowptr[NN + 1];
__device__ int    g_cursor[NN];
__device__ int    g_srcs[EE];
__device__ float  g_ea[EE * 16];
__device__ int    g_binv[EE];
__device__ float  g_fracv[EE];
__device__ float  g_AB[(long long)EE * 128];
__device__ float  g_T[3 * NBINS * 256];
__device__ float  g_TFs[NBINS * 128];
__device__ float2 g_PT[3 * NBINS * 256];
__device__ float2 g_PTF[NBINS * 128];
__device__ float  g_node[NN];

// ---------------------------------------------------------------------------
// init: feat0[:,:,0] = x, rest 0 ; zero degree histogram
// ---------------------------------------------------------------------------
__global__ void k_init(const float* __restrict__ x) {
    int idx = blockIdx.x * blockDim.x + threadIdx.x;
    if (idx < NN * 512) {
        int n = idx >> 9;
        int rem = idx & 511;
        int i = rem & 15;
        int c = rem >> 4;
        g_featA[idx] = (i == 0) ? x[n * 32 + c] : 0.f;
    }
    if (idx < NN) g_deg[idx] = 0;
}

// ---------------------------------------------------------------------------
// degree histogram over active edges (r < RMAX)
// ---------------------------------------------------------------------------
__global__ void k_degree(const float* __restrict__ pos,
                         const int* __restrict__ esrc,
                         const int* __restrict__ edst) {
    int e = blockIdx.x * blockDim.x + threadIdx.x;
    if (e >= EE) return;
    int s = esrc[e], d = edst[e];
    float vx = pos[3 * s + 0] - pos[3 * d + 0];
    float vy = pos[3 * s + 1] - pos[3 * d + 1];
    float vz = pos[3 * s + 2] - pos[3 * d + 2];
    float r2 = vx * vx + vy * vy + vz * vz;
    if (r2 < RMAXF * RMAXF) atomicAdd(&g_deg[d], 1);
}

// ---------------------------------------------------------------------------
// single-block exclusive scan -> rowptr, cursor
// ---------------------------------------------------------------------------
__global__ void k_scan() {
    __shared__ int part[1024];
    const int PER = 10;  // 1024*10 >= NN
    int t = threadIdx.x;
    int base = t * PER;
    int local[PER];
    int s = 0;
    #pragma unroll
    for (int k = 0; k < PER; k++) {
        int idx = base + k;
        int v = (idx < NN) ? g_deg[idx] : 0;
        local[k] = s;
        s += v;
    }
    part[t] = s;
    __syncthreads();
    for (int off = 1; off < 1024; off <<= 1) {
        int v = (t >= off) ? part[t - off] : 0;
        __syncthreads();
        part[t] += v;
        __syncthreads();
    }
    int excl = part[t] - s;
    #pragma unroll
    for (int k = 0; k < PER; k++) {
        int idx = base + k;
        if (idx < NN) {
            g_rowptr[idx] = excl + local[k];
            g_cursor[idx] = excl + local[k];
        }
    }
    if (t == 1023) g_rowptr[NN] = part[1023];
}

// ---------------------------------------------------------------------------
// scatter: sorted-by-dst edge records {src, ea[16], bin, frac}
// ---------------------------------------------------------------------------
__global__ void k_scatter(const float* __restrict__ pos,
                          const int* __restrict__ esrc,
                          const int* __restrict__ edst) {
    int e = blockIdx.x * blockDim.x + threadIdx.x;
    if (e >= EE) return;
    int s = esrc[e], d = edst[e];
    float vx = pos[3 * s + 0] - pos[3 * d + 0];
    float vy = pos[3 * s + 1] - pos[3 * d + 1];
    float vz = pos[3 * s + 2] - pos[3 * d + 2];
    float r2 = vx * vx + vy * vy + vz * vz;
    if (r2 >= RMAXF * RMAXF) return;
    float r = sqrtf(r2);
    float inv = 1.f / (r + 1e-9f);
    float X = vx * inv, Y = vy * inv, Z = vz * inv;
    float cut = 0.5f * (cosf(3.14159265358979f * (r / RMAXF)) + 1.f);

    const float S3 = 1.7320508075688772f;
    const float S15 = 3.872983346207417f;
    const float S5 = 2.23606797749979f;
    const float A4 = 2.091650066335189f;   // sqrt(35/8)
    const float B4 = 10.246950765959598f;  // sqrt(105)
    const float C4 = 1.6201851746019651f;  // sqrt(21/8)
    const float D4 = 1.3228756555322954f;  // sqrt(7)/2

    float X2 = X * X, Y2 = Y * Y, Z2 = Z * Z;

    int p = atomicAdd(&g_cursor[d], 1);
    g_srcs[p] = s;
    float bf = r * ((float)(NBINS - 1) / RMAXF);
    int bi = (int)bf;
    if (bi > NBINS - 2) bi = NBINS - 2;
    g_binv[p] = bi;
    g_fracv[p] = bf - (float)bi;

    float4* ep = (float4*)(g_ea + (long long)p * 16);
    ep[0] = make_float4(cut * 1.f, cut * S3 * X, cut * S3 * Y, cut * S3 * Z);
    ep[1] = make_float4(cut * S15 * X * Y, cut * S15 * Y * Z,
                        cut * 0.5f * S5 * (3.f * Z2 - 1.f), cut * S15 * X * Z);
    ep[2] = make_float4(cut * 0.5f * S15 * (X2 - Y2),
                        cut * A4 * Y * (3.f * X2 - Y2),
                        cut * B4 * X * Y * Z,
                        cut * C4 * Y * (5.f * Z2 - 1.f));
    ep[3] = make_float4(cut * D4 * Z * (5.f * Z2 - 3.f),
                        cut * C4 * X * (5.f * Z2 - 1.f),
                        cut * 0.5f * B4 * Z * (X2 - Y2),
                        cut * A4 * X * (X2 - 3.f * Y2));
}

// ---------------------------------------------------------------------------
// radial-MLP lookup tables: blockIdx.x=bin, blockIdx.y = layer 0..2 | 3=final
// ---------------------------------------------------------------------------
__global__ void k_table(const float* __restrict__ Wr1, const float* __restrict__ Wr2,
                        const float* __restrict__ Wf1, const float* __restrict__ Wf2) {
    int bin = blockIdx.x, m = blockIdx.y, t = threadIdx.x;
    float r = (float)bin * (RMAXF / (float)(NBINS - 1));
    __shared__ float s_emb[10];
    __shared__ float s_h[64];
    if (t < 10) {
        const float step = RMAXF / 9.f;
        float cj = (float)t * step;
        float u = (r - cj) / step;
        s_emb[t] = expf(-u * u) * (3.1622776601683795f / 1.12f);  // sqrt(10)/1.12
    }
    __syncthreads();
    const float* W1 = (m < 3) ? (Wr1 + m * 640) : Wf1;
    {
        float pre = 0.f;
        #pragma unroll
        for (int j = 0; j < 10; j++) pre += s_emb[j] * W1[j * 64 + t];
        pre *= 0.31622776601683794f;  // 1/sqrt(10)
        s_h[t] = pre / (1.f + expf(-pre));  // silu
    }
    __syncthreads();
    if (m < 3) {
        const float* W2 = Wr2 + m * 64 * 256;
        for (int j = t; j < 256; j += 64) {
            float v = 0.f;
            #pragma unroll 8
            for (int k = 0; k < 64; k++) v += s_h[k] * W2[k * 256 + j];
            g_T[((long long)m * NBINS + bin) * 256 + j] = v * 0.125f;
        }
    } else {
        for (int j = t; j < 128; j += 64) {
            float v = 0.f;
            #pragma unroll 8
            for (int k = 0; k < 64; k++) v += s_h[k] * Wf2[k * 128 + j];
            g_TFs[bin * 128 + j] = v * 0.125f;
        }
    }
}

// pack (value, delta-to-next-bin) pairs for one-FMA lerp
__global__ void k_pack() {
    const int T3 = 3 * NBINS * 256;
    int idx = blockIdx.x * blockDim.x + threadIdx.x;
    if (idx < T3) {
        float v = g_T[idx];
        int bin = (idx >> 8) & (NBINS - 1);
        float nx = (bin < NBINS - 1) ? g_T[idx + 256] : v;
        g_PT[idx] = make_float2(v, nx - v);
    } else if (idx < T3 + NBINS * 128) {
        int k = idx - T3;
        float v = g_TFs[k];
        int bin = k >> 7;
        float nx = (bin < NBINS - 1) ? g_TFs[k + 128] : v;
        g_PTF[k] = make_float2(v, nx - v);
    }
}

// ---------------------------------------------------------------------------
// per-layer edge kernel: warp per sorted edge, lane = channel
// writes A,B1,B2,B3 per channel (float4, coalesced)
// ---------------------------------------------------------------------------
__global__ void __launch_bounds__(256) k_edge(int curBuf, int layer) {
    int tot = g_rowptr[NN];
    int warp = threadIdx.x >> 5;
    int lane = threadIdx.x & 31;
    int eg = blockIdx.x * 8 + warp;
    __shared__ float s_ea[8][16];
    if (eg >= tot) return;
    if (lane < 16) s_ea[warp][lane] = g_ea[(long long)eg * 16 + lane];
    __syncwarp();
    const float* feat = curBuf ? g_featB : g_featA;
    int src = g_srcs[eg];
    const float4* fp = (const float4*)(feat + (long long)src * 512 + lane * 16);
    float4 f0 = fp[0], f1 = fp[1], f2 = fp[2], f3 = fp[3];
    float xs0 = f0.x;
    const float* ea = s_ea[warp];
    float d1 = f0.y * ea[1] + f0.z * ea[2] + f0.w * ea[3];
    float d2 = f1.x * ea[4] + f1.y * ea[5] + f1.z * ea[6] + f1.w * ea[7] + f2.x * ea[8];
    float d3 = f2.y * ea[9] + f2.z * ea[10] + f2.w * ea[11] + f3.x * ea[12] +
               f3.y * ea[13] + f3.z * ea[14] + f3.w * ea[15];
    int bin = g_binv[eg];
    float fr = g_fracv[eg];
    const float2* row = g_PT + ((long long)layer * NBINS + bin) * 256;
    float2 p;
    p = row[lane];        float w00 = p.x + fr * p.y;
    p = row[32 + lane];   float w01 = p.x + fr * p.y;
    p = row[64 + lane];   float w02 = p.x + fr * p.y;
    p = row[96 + lane];   float w03 = p.x + fr * p.y;
    p = row[160 + lane];  float w11 = p.x + fr * p.y;
    p = row[192 + lane];  float w12 = p.x + fr * p.y;
    p = row[224 + lane];  float w13 = p.x + fr * p.y;
    float A = w00 * xs0 * ea[0] + w11 * d1 + w12 * d2 + w13 * d3;
    float4 o = make_float4(A, w01 * xs0, w02 * xs0, w03 * xs0);
    ((float4*)(g_AB + (long long)eg * 128))[lane] = o;
}

// ---------------------------------------------------------------------------
// per-layer node kernel: segmented reduce + self-connection + gate
// block = node, 512 threads, thread t -> (o = t>>4, i = t&15)
// ---------------------------------------------------------------------------
__global__ void __launch_bounds__(512) k_agg(int curBuf, const float* __restrict__ Wsc) {
    int n = blockIdx.x;
    int t = threadIdx.x;
    int o = t >> 4, i = t & 15;
    const float* featC = curBuf ? g_featB : g_featA;
    float* featN = curBuf ? g_featA : g_featB;

    __shared__ float s_feat[512];
    __shared__ float s_w[4 * 1032];       // padded stride to dodge bank conflicts
    __shared__ float s_e[4 * 128];
    __shared__ float s_ee[4 * 16];
    __shared__ float s_y[512];

    s_feat[t] = featC[(long long)n * 512 + t];
    for (int g = t; g < 4096; g += 512) s_w[(g >> 10) * 1032 + (g & 1023)] = Wsc[g];
    __syncthreads();

    int l = (i == 0) ? 0 : (i < 4) ? 1 : (i < 9) ? 2 : 3;
    float sc = 0.f;
    {
        const float* wl = &s_w[l * 1032 + o];
        const float* fi = &s_feat[i];
        #pragma unroll
        for (int cc = 0; cc < 32; cc++) sc += fi[cc * 16] * wl[cc * 32];
        sc *= INV_SQRT32;
    }

    int e0 = g_rowptr[n], e1 = g_rowptr[n + 1];
    float acc = 0.f;
    int sel = (i == 0) ? 0 : l;
    for (int base = e0; base < e1; base += 4) {
        int nl = min(4, e1 - base);
        if (t < nl * 128) s_e[t] = g_AB[(long long)base * 128 + t];
        if (t < nl * 16) s_ee[t] = g_ea[(long long)base * 16 + t];
        __syncthreads();
        for (int j = 0; j < nl; j++) {
            float coef = s_e[j * 128 + (o << 2) + sel];
            acc += (i == 0) ? coef : coef * s_ee[j * 16 + i];
        }
        __syncthreads();
    }

    float y = sc + acc * INV_SQRT_NAVG;
    s_y[t] = y;
    __syncthreads();
    float s = s_y[o << 4];
    float sg = 1.f / (1.f + expf(-s));
    featN[(long long)n * 512 + t] = (i == 0) ? s * sg : y * sg;
}

// ---------------------------------------------------------------------------
// final readout: per-node scalar via table-lerped wf
// ---------------------------------------------------------------------------
__global__ void __launch_bounds__(128) k_final(int curBuf) {
    int n = blockIdx.x;
    int warp = threadIdx.x >> 5, lane = threadIdx.x & 31;
    const float* featC = curBuf ? g_featB : g_featA;
    __shared__ float s_ea[4][16];
    __shared__ float s_acc;
    if (threadIdx.x == 0) s_acc = 0.f;
    __syncthreads();
    int e0 = g_rowptr[n], e1 = g_rowptr[n + 1];
    float acc = 0.f;
    for (int eg = e0 + warp; eg < e1; eg += 4) {
        if (lane < 16) s_ea[warp][lane] = g_ea[(long long)eg * 16 + lane];
        __syncwarp();
        int src = g_srcs[eg];
        const float4* fp = (const float4*)(featC + (long long)src * 512 + lane * 16);
        float4 f0 = fp[0], f1 = fp[1], f2 = fp[2], f3 = fp[3];
        const float* ea = s_ea[warp];
        float d1 = f0.y * ea[1] + f0.z * ea[2] + f0.w * ea[3];
        float d2 = f1.x * ea[4] + f1.y * ea[5] + f1.z * ea[6] + f1.w * ea[7] + f2.x * ea[8];
        float d3 = f2.y * ea[9] + f2.z * ea[10] + f2.w * ea[11] + f3.x * ea[12] +
                   f3.y * ea[13] + f3.z * ea[14] + f3.w * ea[15];
        int bin = g_binv[eg];
        float fr = g_fracv[eg];
        const float2* row = g_PTF + (long long)bin * 128;
        float2 p;
        p = row[lane];       float w0 = p.x + fr * p.y;
        p = row[32 + lane];  float w1 = p.x + fr * p.y;
        p = row[64 + lane];  float w2 = p.x + fr * p.y;
        p = row[96 + lane];  float w3 = p.x + fr * p.y;
        acc += w0 * f0.x * ea[0] + w1 * d1 + w2 * d2 + w3 * d3;
        __syncwarp();
    }
    #pragma unroll
    for (int off = 16; off; off >>= 1) acc += __shfl_down_sync(0xffffffff, acc, off);
    if (lane == 0) atomicAdd(&s_acc, acc);
    __syncthreads();
    if (threadIdx.x == 0) g_node[n] = s_acc * (INV_SQRT32 * INV_SQRT_NAVG);
}

// ---------------------------------------------------------------------------
// graph readout (16 outputs), single block
// ---------------------------------------------------------------------------
__global__ void k_out(const int* __restrict__ batch, float* __restrict__ out) {
    __shared__ float s[16];
    int t = threadIdx.x;
    if (t < 16) s[t] = 0.f;
    __syncthreads();
    for (int n = t; n < NN; n += blockDim.x) atomicAdd(&s[batch[n]], g_node[n]);
    __syncthreads();
    if (t < 16) out[t] = s[t] * INV_SQRT_NAVG;
}

// ---------------------------------------------------------------------------
extern "C" void kernel_launch(void* const* d_in, const int* in_sizes, int n_in,
                              void* d_out, int out_size) {
    const float* pos  = (const float*)d_in[0];
    const float* x    = (const float*)d_in[1];
    const int*   batch= (const int*)d_in[2];
    const int*   esrc = (const int*)d_in[3];
    const int*   edst = (const int*)d_in[4];
    const float* Wsc  = (const float*)d_in[5];
    const float* Wr1  = (const float*)d_in[6];
    const float* Wr2  = (const float*)d_in[7];
    const float* Wf1  = (const float*)d_in[8];
    const float* Wf2  = (const float*)d_in[9];
    float* out = (float*)d_out;

    k_init<<<(NN * 512 + 255) / 256, 256>>>(x);
    k_degree<<<(EE + 255) / 256, 256>>>(pos, esrc, edst);
    k_scan<<<1, 1024>>>();
    k_scatter<<<(EE + 255) / 256, 256>>>(pos, esrc, edst);
    k_table<<<dim3(NBINS, 4), 64>>>(Wr1, Wr2, Wf1, Wf2);
    k_pack<<<(3 * NBINS * 256 + NBINS * 128 + 255) / 256, 256>>>();

    // layer 0: A -> B ; layer 1: B -> A ; layer 2: A -> B
    int cur = 0;
    for (int L = 0; L < 3; L++) {
        k_edge<<<(EE + 7) / 8, 256>>>(cur, L);
        k_agg<<<NN, 512>>>(cur, Wsc + (long long)L * 4 * 32 * 32);
        cur ^= 1;
    }
    k_final<<<NN, 128>>>(cur);  // cur == 1 -> featB
    k_out<<<1, 1024>>>(batch, out);
}

// round 6
// speedup vs baseline: 1.0035x; 1.0035x over previous
#include <cuda_runtime.h>
#include <math.h>

#define NN 10000
#define EE 256000
#define NBINS 2048
#define RMAXF 3.5f
#define INV_SQRT32 0.17677669529663687f
#define INV_SQRT_NAVG 0.19764235376052372f

// ---- static device scratch (no allocations allowed) ----
__device__ float  g_featA[NN * 512];
__device__ float  g_featB[NN * 512];
__device__ int    g_deg[NN];
__device__ int    g_rowptr[NN + 1];
__device__ int    g_cursor[NN];
__device__ int    g_srcs[EE];
__device__ float  g_ea[EE * 16];
__device__ int    g_binv[EE];
__device__ float  g_fracv[EE];
__device__ float  g_AB[(long long)EE * 128];
__device__ float  g_T[3 * NBINS * 256];
__device__ float  g_TFs[NBINS * 128];
__device__ float2 g_PT[3 * NBINS * 256];
__device__ float2 g_PTF[NBINS * 128];
__device__ float  g_node[NN];

// ---------------------------------------------------------------------------
// init: feat0[:,:,0] = x, rest 0 ; zero degree histogram
// ---------------------------------------------------------------------------
__global__ void k_init(const float* __restrict__ x) {
    int idx = blockIdx.x * blockDim.x + threadIdx.x;
    if (idx < NN * 512) {
        int n = idx >> 9;
        int rem = idx & 511;
        int i = rem & 15;
        int c = rem >> 4;
        g_featA[idx] = (i == 0) ? x[n * 32 + c] : 0.f;
    }
    if (idx < NN) g_deg[idx] = 0;
}

// ---------------------------------------------------------------------------
// degree histogram over active edges (r < RMAX)
// ---------------------------------------------------------------------------
__global__ void k_degree(const float* __restrict__ pos,
                         const int* __restrict__ esrc,
                         const int* __restrict__ edst) {
    int e = blockIdx.x * blockDim.x + threadIdx.x;
    if (e >= EE) return;
    int s = esrc[e], d = edst[e];
    float vx = pos[3 * s + 0] - pos[3 * d + 0];
    float vy = pos[3 * s + 1] - pos[3 * d + 1];
    float vz = pos[3 * s + 2] - pos[3 * d + 2];
    float r2 = vx * vx + vy * vy + vz * vz;
    if (r2 < RMAXF * RMAXF) atomicAdd(&g_deg[d], 1);
}

// ---------------------------------------------------------------------------
// single-block exclusive scan -> rowptr, cursor
// ---------------------------------------------------------------------------
__global__ void k_scan() {
    __shared__ int part[1024];
    const int PER = 10;  // 1024*10 >= NN
    int t = threadIdx.x;
    int base = t * PER;
    int local[PER];
    int s = 0;
    #pragma unroll
    for (int k = 0; k < PER; k++) {
        int idx = base + k;
        int v = (idx < NN) ? g_deg[idx] : 0;
        local[k] = s;
        s += v;
    }
    part[t] = s;
    __syncthreads();
    for (int off = 1; off < 1024; off <<= 1) {
        int v = (t >= off) ? part[t - off] : 0;
        __syncthreads();
        part[t] += v;
        __syncthreads();
    }
    int excl = part[t] - s;
    #pragma unroll
    for (int k = 0; k < PER; k++) {
        int idx = base + k;
        if (idx < NN) {
            g_rowptr[idx] = excl + local[k];
            g_cursor[idx] = excl + local[k];
        }
    }
    if (t == 1023) g_rowptr[NN] = part[1023];
}

// ---------------------------------------------------------------------------
// scatter: sorted-by-dst edge records {src, ea[16], bin, frac}
// ---------------------------------------------------------------------------
__global__ void k_scatter(const float* __restrict__ pos,
                          const int* __restrict__ esrc,
                          const int* __restrict__ edst) {
    int e = blockIdx.x * blockDim.x + threadIdx.x;
    if (e >= EE) return;
    int s = esrc[e], d = edst[e];
    float vx = pos[3 * s + 0] - pos[3 * d + 0];
    float vy = pos[3 * s + 1] - pos[3 * d + 1];
    float vz = pos[3 * s + 2] - pos[3 * d + 2];
    float r2 = vx * vx + vy * vy + vz * vz;
    if (r2 >= RMAXF * RMAXF) return;
    float r = sqrtf(r2);
    float inv = 1.f / (r + 1e-9f);
    float X = vx * inv, Y = vy * inv, Z = vz * inv;
    float cut = 0.5f * (cosf(3.14159265358979f * (r / RMAXF)) + 1.f);

    const float S3 = 1.7320508075688772f;
    const float S15 = 3.872983346207417f;
    const float S5 = 2.23606797749979f;
    const float A4 = 2.091650066335189f;   // sqrt(35/8)
    const float B4 = 10.246950765959598f;  // sqrt(105)
    const float C4 = 1.6201851746019651f;  // sqrt(21/8)
    const float D4 = 1.3228756555322954f;  // sqrt(7)/2

    float X2 = X * X, Y2 = Y * Y, Z2 = Z * Z;

    int p = atomicAdd(&g_cursor[d], 1);
    g_srcs[p] = s;
    float bf = r * ((float)(NBINS - 1) / RMAXF);
    int bi = (int)bf;
    if (bi > NBINS - 2) bi = NBINS - 2;
    g_binv[p] = bi;
    g_fracv[p] = bf - (float)bi;

    float4* ep = (float4*)(g_ea + (long long)p * 16);
    ep[0] = make_float4(cut * 1.f, cut * S3 * X, cut * S3 * Y, cut * S3 * Z);
    ep[1] = make_float4(cut * S15 * X * Y, cut * S15 * Y * Z,
                        cut * 0.5f * S5 * (3.f * Z2 - 1.f), cut * S15 * X * Z);
    ep[2] = make_float4(cut * 0.5f * S15 * (X2 - Y2),
                        cut * A4 * Y * (3.f * X2 - Y2),
                        cut * B4 * X * Y * Z,
                        cut * C4 * Y * (5.f * Z2 - 1.f));
    ep[3] = make_float4(cut * D4 * Z * (5.f * Z2 - 3.f),
                        cut * C4 * X * (5.f * Z2 - 1.f),
                        cut * 0.5f * B4 * Z * (X2 - Y2),
                        cut * A4 * X * (X2 - 3.f * Y2));
}

// ---------------------------------------------------------------------------
// radial-MLP lookup tables: blockIdx.x=bin, blockIdx.y = layer 0..2 | 3=final
// ---------------------------------------------------------------------------
__global__ void k_table(const float* __restrict__ Wr1, const float* __restrict__ Wr2,
                        const float* __restrict__ Wf1, const float* __restrict__ Wf2) {
    int bin = blockIdx.x, m = blockIdx.y, t = threadIdx.x;
    float r = (float)bin * (RMAXF / (float)(NBINS - 1));
    __shared__ float s_emb[10];
    __shared__ float s_h[64];
    if (t < 10) {
        const float step = RMAXF / 9.f;
        float cj = (float)t * step;
        float u = (r - cj) / step;
        s_emb[t] = expf(-u * u) * (3.1622776601683795f / 1.12f);  // sqrt(10)/1.12
    }
    __syncthreads();
    const float* W1 = (m < 3) ? (Wr1 + m * 640) : Wf1;
    {
        float pre = 0.f;
        #pragma unroll
        for (int j = 0; j < 10; j++) pre += s_emb[j] * W1[j * 64 + t];
        pre *= 0.31622776601683794f;  // 1/sqrt(10)
        s_h[t] = pre / (1.f + expf(-pre));  // silu
    }
    __syncthreads();
    if (m < 3) {
        const float* W2 = Wr2 + m * 64 * 256;
        for (int j = t; j < 256; j += 64) {
            float v = 0.f;
            #pragma unroll 8
            for (int k = 0; k < 64; k++) v += s_h[k] * W2[k * 256 + j];
            g_T[((long long)m * NBINS + bin) * 256 + j] = v * 0.125f;
        }
    } else {
        for (int j = t; j < 128; j += 64) {
            float v = 0.f;
            #pragma unroll 8
            for (int k = 0; k < 64; k++) v += s_h[k] * Wf2[k * 128 + j];
            g_TFs[bin * 128 + j] = v * 0.125f;
        }
    }
}

// pack (value, delta-to-next-bin) pairs for one-FMA lerp
__global__ void k_pack() {
    const int T3 = 3 * NBINS * 256;
    int idx = blockIdx.x * blockDim.x + threadIdx.x;
    if (idx < T3) {
        float v = g_T[idx];
        int bin = (idx >> 8) & (NBINS - 1);
        float nx = (bin < NBINS - 1) ? g_T[idx + 256] : v;
        g_PT[idx] = make_float2(v, nx - v);
    } else if (idx < T3 + NBINS * 128) {
        int k = idx - T3;
        float v = g_TFs[k];
        int bin = k >> 7;
        float nx = (bin < NBINS - 1) ? g_TFs[k + 128] : v;
        g_PTF[k] = make_float2(v, nx - v);
    }
}

// ---------------------------------------------------------------------------
// per-layer edge kernel: warp per sorted edge, lane = channel
// writes A,B1,B2,B3 per channel (float4, coalesced)
// ---------------------------------------------------------------------------
__global__ void __launch_bounds__(256) k_edge(int curBuf, int layer) {
    int tot = g_rowptr[NN];
    int warp = threadIdx.x >> 5;
    int lane = threadIdx.x & 31;
    int eg = blockIdx.x * 8 + warp;
    __shared__ float s_ea[8][16];
    if (eg >= tot) return;
    if (lane < 16) s_ea[warp][lane] = g_ea[(long long)eg * 16 + lane];
    __syncwarp();
    const float* feat = curBuf ? g_featB : g_featA;
    int src = g_srcs[eg];
    const float4* fp = (const float4*)(feat + (long long)src * 512 + lane * 16);
    float4 f0 = fp[0], f1 = fp[1], f2 = fp[2], f3 = fp[3];
    float xs0 = f0.x;
    const float* ea = s_ea[warp];
    float d1 = f0.y * ea[1] + f0.z * ea[2] + f0.w * ea[3];
    float d2 = f1.x * ea[4] + f1.y * ea[5] + f1.z * ea[6] + f1.w * ea[7] + f2.x * ea[8];
    float d3 = f2.y * ea[9] + f2.z * ea[10] + f2.w * ea[11] + f3.x * ea[12] +
               f3.y * ea[13] + f3.z * ea[14] + f3.w * ea[15];
    int bin = g_binv[eg];
    float fr = g_fracv[eg];
    const float2* row = g_PT + ((long long)layer * NBINS + bin) * 256;
    float2 p;
    p = row[lane];        float w00 = p.x + fr * p.y;
    p = row[32 + lane];   float w01 = p.x + fr * p.y;
    p = row[64 + lane];   float w02 = p.x + fr * p.y;
    p = row[96 + lane];   float w03 = p.x + fr * p.y;
    p = row[160 + lane];  float w11 = p.x + fr * p.y;
    p = row[192 + lane];  float w12 = p.x + fr * p.y;
    p = row[224 + lane];  float w13 = p.x + fr * p.y;
    float A = w00 * xs0 * ea[0] + w11 * d1 + w12 * d2 + w13 * d3;
    float4 o = make_float4(A, w01 * xs0, w02 * xs0, w03 * xs0);
    ((float4*)(g_AB + (long long)eg * 128))[lane] = o;
}

// ---------------------------------------------------------------------------
// per-layer node kernel: segmented reduce + self-connection + gate
// block = node, 512 threads, thread t -> (o = t>>4, i = t&15)
// ---------------------------------------------------------------------------
__global__ void __launch_bounds__(512) k_agg(int curBuf, const float* __restrict__ Wsc) {
    int n = blockIdx.x;
    int t = threadIdx.x;
    int o = t >> 4, i = t & 15;
    const float* featC = curBuf ? g_featB : g_featA;
    float* featN = curBuf ? g_featA : g_featB;

    __shared__ float s_feat[512];
    __shared__ float s_w[4 * 1032];       // padded stride to dodge bank conflicts
    __shared__ float s_e[4 * 128];
    __shared__ float s_ee[4 * 16];
    __shared__ float s_y[512];

    s_feat[t] = featC[(long long)n * 512 + t];
    for (int g = t; g < 4096; g += 512) s_w[(g >> 10) * 1032 + (g & 1023)] = Wsc[g];
    __syncthreads();

    int l = (i == 0) ? 0 : (i < 4) ? 1 : (i < 9) ? 2 : 3;
    float sc = 0.f;
    {
        const float* wl = &s_w[l * 1032 + o];
        const float* fi = &s_feat[i];
        #pragma unroll
        for (int cc = 0; cc < 32; cc++) sc += fi[cc * 16] * wl[cc * 32];
        sc *= INV_SQRT32;
    }

    int e0 = g_rowptr[n], e1 = g_rowptr[n + 1];
    float acc = 0.f;
    int sel = (i == 0) ? 0 : l;
    for (int base = e0; base < e1; base += 4) {
        int nl = min(4, e1 - base);
        if (t < nl * 128) s_e[t] = g_AB[(long long)base * 128 + t];
        if (t < nl * 16) s_ee[t] = g_ea[(long long)base * 16 + t];
        __syncthreads();
        for (int j = 0; j < nl; j++) {
            float coef = s_e[j * 128 + (o << 2) + sel];
            acc += (i == 0) ? coef : coef * s_ee[j * 16 + i];
        }
        __syncthreads();
    }

    float y = sc + acc * INV_SQRT_NAVG;
    s_y[t] = y;
    __syncthreads();
    float s = s_y[o << 4];
    float sg = 1.f / (1.f + expf(-s));
    featN[(long long)n * 512 + t] = (i == 0) ? s * sg : y * sg;
}

// ---------------------------------------------------------------------------
// final readout: per-node scalar via table-lerped wf
// ---------------------------------------------------------------------------
__global__ void __launch_bounds__(128) k_final(int curBuf) {
    int n = blockIdx.x;
    int warp = threadIdx.x >> 5, lane = threadIdx.x & 31;
    const float* featC = curBuf ? g_featB : g_featA;
    __shared__ float s_ea[4][16];
    __shared__ float s_acc;
    if (threadIdx.x == 0) s_acc = 0.f;
    __syncthreads();
    int e0 = g_rowptr[n], e1 = g_rowptr[n + 1];
    float acc = 0.f;
    for (int eg = e0 + warp; eg < e1; eg += 4) {
        if (lane < 16) s_ea[warp][lane] = g_ea[(long long)eg * 16 + lane];
        __syncwarp();
        int src = g_srcs[eg];
        const float4* fp = (const float4*)(featC + (long long)src * 512 + lane * 16);
        float4 f0 = fp[0], f1 = fp[1], f2 = fp[2], f3 = fp[3];
        const float* ea = s_ea[warp];
        float d1 = f0.y * ea[1] + f0.z * ea[2] + f0.w * ea[3];
        float d2 = f1.x * ea[4] + f1.y * ea[5] + f1.z * ea[6] + f1.w * ea[7] + f2.x * ea[8];
        float d3 = f2.y * ea[9] + f2.z * ea[10] + f2.w * ea[11] + f3.x * ea[12] +
                   f3.y * ea[13] + f3.z * ea[14] + f3.w * ea[15];
        int bin = g_binv[eg];
        float fr = g_fracv[eg];
        const float2* row = g_PTF + (long long)bin * 128;
        float2 p;
        p = row[lane];       float w0 = p.x + fr * p.y;
        p = row[32 + lane];  float w1 = p.x + fr * p.y;
        p = row[64 + lane];  float w2 = p.x + fr * p.y;
        p = row[96 + lane];  float w3 = p.x + fr * p.y;
        acc += w0 * f0.x * ea[0] + w1 * d1 + w2 * d2 + w3 * d3;
        __syncwarp();
    }
    #pragma unroll
    for (int off = 16; off; off >>= 1) acc += __shfl_down_sync(0xffffffff, acc, off);
    if (lane == 0) atomicAdd(&s_acc, acc);
    __syncthreads();
    if (threadIdx.x == 0) g_node[n] = s_acc * (INV_SQRT32 * INV_SQRT_NAVG);
}

// ---------------------------------------------------------------------------
// graph readout (16 outputs), single block
// ---------------------------------------------------------------------------
__global__ void k_out(const int* __restrict__ batch, float* __restrict__ out) {
    __shared__ float s[16];
    int t = threadIdx.x;
    if (t < 16) s[t] = 0.f;
    __syncthreads();
    for (int n = t; n < NN; n += blockDim.x) atomicAdd(&s[batch[n]], g_node[n]);
    __syncthreads();
    if (t < 16) out[t] = s[t] * INV_SQRT_NAVG;
}

// ---------------------------------------------------------------------------
extern "C" void kernel_launch(void* const* d_in, const int* in_sizes, int n_in,
                              void* d_out, int out_size) {
    const float* pos  = (const float*)d_in[0];
    const float* x    = (const float*)d_in[1];
    const int*   batch= (const int*)d_in[2];
    const int*   esrc = (const int*)d_in[3];
    const int*   edst = (const int*)d_in[4];
    const float* Wsc  = (const float*)d_in[5];
    const float* Wr1  = (const float*)d_in[6];
    const float* Wr2  = (const float*)d_in[7];
    const float* Wf1  = (const float*)d_in[8];
    const float* Wf2  = (const float*)d_in[9];
    float* out = (float*)d_out;

    k_init<<<(NN * 512 + 255) / 256, 256>>>(x);
    k_degree<<<(EE + 255) / 256, 256>>>(pos, esrc, edst);
    k_scan<<<1, 1024>>>();
    k_scatter<<<(EE + 255) / 256, 256>>>(pos, esrc, edst);
    k_table<<<dim3(NBINS, 4), 64>>>(Wr1, Wr2, Wf1, Wf2);
    k_pack<<<(3 * NBINS * 256 + NBINS * 128 + 255) / 256, 256>>>();

    // layer 0: A -> B ; layer 1: B -> A ; layer 2: A -> B
    int cur = 0;
    for (int L = 0; L < 3; L++) {
        k_edge<<<(EE + 7) / 8, 256>>>(cur, L);
        k_agg<<<NN, 512>>>(cur, Wsc + (long long)L * 4 * 32 * 32);
        cur ^= 1;
    }
    k_final<<<NN, 128>>>(cur);  // cur == 1 -> featB
    k_out<<<1, 1024>>>(batch, out);
}